// round 8
// baseline (speedup 1.0000x reference)
#include <cuda_runtime.h>
#include <cuda_bf16.h>
#include <math.h>
#include <stdint.h>

// Problem constants
#define TOKENS 2048
#define HID 256
#define NB 41
#define CBIN 123
#define OUTC (CBIN * HID)    // 31488
#define OPT (NB * NB * NB)   // 68921
#define NXZ (NB * NB)        // 1681

// Scratch: bin = softplus(emb @ W^T + b), token-major bf16
__device__ __nv_bfloat16 g_bin[(size_t)TOKENS * OUTC];

// ---------------------------------------------------------------------------
// Common PTX helpers
// ---------------------------------------------------------------------------
__device__ __forceinline__ uint32_t smem_u32(const void* p) {
    uint32_t a;
    asm("{ .reg .u64 t; cvta.to.shared.u64 t, %1; cvt.u32.u64 %0, t; }"
        : "=r"(a) : "l"(p));
    return a;
}
__device__ __forceinline__ void cp16(uint32_t s, const void* g) {
    asm volatile("cp.async.cg.shared.global [%0], [%1], 16;"
                 :: "r"(s), "l"(g) : "memory");
}
__device__ __forceinline__ void cp_commit() {
    asm volatile("cp.async.commit_group;" ::: "memory");
}
template <int N>
__device__ __forceinline__ void cp_wait() {
    asm volatile("cp.async.wait_group %0;" :: "n"(N) : "memory");
}

// ---------------------------------------------------------------------------
// Stage 1: tf32 tensor-core GEMM + softplus + bf16 store
//   C[t, o] = softplus( sum_k emb[t,k] * W[o,k] + b[o] )
//   Raw f32 bits fed to HMMA.tf32 (hardware truncates to tf32) — no cvt.
//   cp.async 4-stage pipeline, CTA tile 128(t) x 128(o), BK=16,
//   8 warps of 64x32.
// ---------------------------------------------------------------------------
#define S1_PAD 20                 // row stride in u32
#define S1_STG 4
#define S1_TILE (128 * S1_PAD)    // u32 per tile per stage
#define SM1_BYTES (2 * S1_STG * S1_TILE * 4)   // 81920

__device__ __forceinline__ void mma16808(float* d, const uint32_t* a,
                                         const uint32_t* b) {
    asm volatile(
        "mma.sync.aligned.m16n8k8.row.col.f32.tf32.tf32.f32 "
        "{%0,%1,%2,%3}, {%4,%5,%6,%7}, {%8,%9}, {%0,%1,%2,%3};"
        : "+f"(d[0]), "+f"(d[1]), "+f"(d[2]), "+f"(d[3])
        : "r"(a[0]), "r"(a[1]), "r"(a[2]), "r"(a[3]), "r"(b[0]), "r"(b[1]));
}
__device__ __forceinline__ float softplusf(float x) {
    return fmaxf(x, 0.0f) + log1pf(expf(-fabsf(x)));
}

__global__ void __launch_bounds__(256, 2) gemm_softplus_tf32(
    const float* __restrict__ W, const float* __restrict__ emb,
    const float* __restrict__ bias)
{
    extern __shared__ uint32_t s1[];
    uint32_t* As = s1;                       // [S1_STG][S1_TILE]  emb tiles
    uint32_t* Bs = s1 + S1_STG * S1_TILE;    // [S1_STG][S1_TILE]  W tiles

    const int t0 = blockIdx.y * 128;
    const int o0 = blockIdx.x * 128;
    const int tid = threadIdx.x;
    const int wid = tid >> 5, lane = tid & 31;
    const int wm = (wid & 1) * 64;       // t offset of warp tile
    const int wn = (wid >> 1) * 32;      // o offset of warp tile
    const int r = lane >> 2, c = lane & 3;

    // Loader mapping: row = tid>>1 (0..127), quarters {q, q+2}, q = tid&1
    const int lrow = tid >> 1;
    const int q0 = (tid & 1) * 4;        // f32 col offset 0 or 4
    const int q1 = q0 + 8;               // f32 col offset 8 or 12
    const float* embRow = emb + (size_t)(t0 + lrow) * HID;
    const float* wRow = W + (size_t)(o0 + lrow) * HID;
    const uint32_t asmA = smem_u32(As) + (uint32_t)(lrow * S1_PAD) * 4u;
    const uint32_t asmB = smem_u32(Bs) + (uint32_t)(lrow * S1_PAD) * 4u;

    float acc[4][4][4];
    #pragma unroll
    for (int mt = 0; mt < 4; mt++)
        #pragma unroll
        for (int nt = 0; nt < 4; nt++)
            #pragma unroll
            for (int qq = 0; qq < 4; qq++) acc[mt][nt][qq] = 0.0f;

    // Prologue: issue stages 0..2
    #pragma unroll
    for (int s = 0; s < 3; s++) {
        const int k0 = s * 16;
        const uint32_t so = (uint32_t)(s * S1_TILE) * 4u;
        cp16(asmA + so + q0 * 4u, embRow + k0 + q0);
        cp16(asmA + so + q1 * 4u, embRow + k0 + q1);
        cp16(asmB + so + q0 * 4u, wRow + k0 + q0);
        cp16(asmB + so + q1 * 4u, wRow + k0 + q1);
        cp_commit();
    }

    #pragma unroll 1
    for (int it = 0; it < 16; it++) {
        if (it < 14) cp_wait<2>();
        else if (it == 14) cp_wait<1>();
        else cp_wait<0>();
        __syncthreads();

        if (it + 3 < 16) {
            const int s = (it + 3) & 3;
            const int k0 = (it + 3) * 16;
            const uint32_t so = (uint32_t)(s * S1_TILE) * 4u;
            cp16(asmA + so + q0 * 4u, embRow + k0 + q0);
            cp16(asmA + so + q1 * 4u, embRow + k0 + q1);
            cp16(asmB + so + q0 * 4u, wRow + k0 + q0);
            cp16(asmB + so + q1 * 4u, wRow + k0 + q1);
            cp_commit();
        }

        const uint32_t* Ac = As + (it & 3) * S1_TILE;
        const uint32_t* Bc = Bs + (it & 3) * S1_TILE;
        #pragma unroll
        for (int kk = 0; kk < 2; kk++) {
            const int kb = kk * 8;
            uint32_t a[4][4], b[4][2];
            #pragma unroll
            for (int mt = 0; mt < 4; mt++) {
                const uint32_t* p = &Ac[(wm + mt * 16 + r) * S1_PAD + kb + c];
                a[mt][0] = p[0];
                a[mt][1] = p[8 * S1_PAD];
                a[mt][2] = p[4];
                a[mt][3] = p[8 * S1_PAD + 4];
            }
            #pragma unroll
            for (int nt = 0; nt < 4; nt++) {
                const uint32_t* p = &Bc[(wn + nt * 8 + r) * S1_PAD + kb + c];
                b[nt][0] = p[0];
                b[nt][1] = p[4];
            }
            #pragma unroll
            for (int mt = 0; mt < 4; mt++)
                #pragma unroll
                for (int nt = 0; nt < 4; nt++)
                    mma16808(acc[mt][nt], a[mt], b[nt]);
        }
    }

    // Epilogue: +bias, softplus, pack bf16x2, store token-major
    uint32_t* gb = (uint32_t*)g_bin;
    #pragma unroll
    for (int mt = 0; mt < 4; mt++) {
        const int tA = t0 + wm + mt * 16 + r;
        const size_t row0 = (size_t)tA * (OUTC / 2);
        const size_t row1 = (size_t)(tA + 8) * (OUTC / 2);
        #pragma unroll
        for (int nt = 0; nt < 4; nt++) {
            const int o = o0 + wn + nt * 8 + 2 * c;
            const float2 bi = *(const float2*)(bias + o);
            float s0 = softplusf(acc[mt][nt][0] + bi.x);
            float s1 = softplusf(acc[mt][nt][1] + bi.y);
            float s2 = softplusf(acc[mt][nt][2] + bi.x);
            float s3 = softplusf(acc[mt][nt][3] + bi.y);
            __nv_bfloat162 p0 = __float22bfloat162_rn(make_float2(s0, s1));
            __nv_bfloat162 p1 = __float22bfloat162_rn(make_float2(s2, s3));
            gb[row0 + (o >> 1)] = *(uint32_t*)&p0;
            gb[row1 + (o >> 1)] = *(uint32_t*)&p1;
        }
    }
}

// ---------------------------------------------------------------------------
// Stage 2: per-token triple contraction via warp mma.sync (bf16, f32 acc)
//   Job = (z-tile of 16, x-pair): ey fragments amortized over 2 x values.
//   (unchanged — measured at the mma.sync HMMA ceiling)
// ---------------------------------------------------------------------------
#define RS 132           // SMEM row stride in u32 (132 % 32 == 4)
#define EYB 41
#define EZB 89
#define SM2_U32 (137 * RS)
#define SM2_BYTES (SM2_U32 * 4)   // 72336

__device__ __forceinline__ uint32_t bmul2(uint32_t a, uint32_t b) {
    uint32_t d;
    asm("mul.bf16x2 %0, %1, %2;" : "=r"(d) : "r"(a), "r"(b));
    return d;
}
__device__ __forceinline__ void mma16816(float* d,
                                         uint32_t a0, uint32_t a1,
                                         uint32_t a2, uint32_t a3,
                                         uint32_t b0, uint32_t b1) {
    asm volatile(
        "mma.sync.aligned.m16n8k16.row.col.f32.bf16.bf16.f32 "
        "{%0,%1,%2,%3}, {%4,%5,%6,%7}, {%8,%9}, {%0,%1,%2,%3};"
        : "+f"(d[0]), "+f"(d[1]), "+f"(d[2]), "+f"(d[3])
        : "r"(a0), "r"(a1), "r"(a2), "r"(a3), "r"(b0), "r"(b1));
}

__global__ void __launch_bounds__(256, 2) triple_mma_kernel(
    const float* __restrict__ ls, float* __restrict__ out)
{
    extern __shared__ uint32_t sm[];
    const int tid = threadIdx.x;
    const int wid = tid >> 5;
    const int lid = tid & 31;
    const int rowin = lid >> 2;
    const int qc = lid & 3;
    const int t = blockIdx.x;

    const uint4* src = (const uint4*)(g_bin + (size_t)t * OUTC);
    for (int i = tid; i < CBIN * 32; i += 256) {
        const int cc = i >> 5;
        const int j = i & 31;
        const int dr = cc + (cc >= 82 ? 7 : 0);
        *(uint4*)&sm[dr * RS + j * 4] = src[i];
    }
    for (int i = tid; i < 7 * RS; i += 256) {
        sm[82 * RS + i] = 0u;
        sm[130 * RS + i] = 0u;
    }
    __syncthreads();

    const float scale = expf(ls[0]);
    float* __restrict__ outT = out + (size_t)t * OPT;

    for (int j = wid; j < 63; j += 8) {
        const int zt = j / 21;
        const int xp = j - zt * 21;
        const int x0 = 2 * xp;
        const bool hasx1 = (x0 + 1 < NB);
        const int x1 = hasx1 ? (x0 + 1) : (NB - 1);
        const int z0 = zt * 16;

        float acc[2][6][4];
        #pragma unroll
        for (int xi = 0; xi < 2; xi++)
            #pragma unroll
            for (int g = 0; g < 6; g++)
                #pragma unroll
                for (int qq = 0; qq < 4; qq++) acc[xi][g][qq] = 0.0f;

        const uint32_t* __restrict__ ex0p = sm + x0 * RS;
        const uint32_t* __restrict__ ex1p = sm + x1 * RS;
        const uint32_t* __restrict__ ezA = sm + (EZB + z0 + rowin) * RS;
        const uint32_t* __restrict__ ezB = ezA + 8 * RS;
        const uint32_t* __restrict__ eyp = sm + (EYB + rowin) * RS;

        #pragma unroll
        for (int k = 0; k < 16; k++) {
            const int c0 = k * 8 + qc;
            const int c1 = c0 + 4;
            const uint32_t ez0 = ezA[c0], ez1 = ezB[c0];
            const uint32_t ez2 = ezA[c1], ez3 = ezB[c1];
            const uint32_t exa0 = ex0p[c0], exa1 = ex0p[c1];
            const uint32_t exb0 = ex1p[c0], exb1 = ex1p[c1];
            const uint32_t A00 = bmul2(ez0, exa0), A01 = bmul2(ez1, exa0);
            const uint32_t A02 = bmul2(ez2, exa1), A03 = bmul2(ez3, exa1);
            const uint32_t A10 = bmul2(ez0, exb0), A11 = bmul2(ez1, exb0);
            const uint32_t A12 = bmul2(ez2, exb1), A13 = bmul2(ez3, exb1);
            #pragma unroll
            for (int g = 0; g < 6; g++) {
                const uint32_t b0 = eyp[g * 8 * RS + c0];
                const uint32_t b1 = eyp[g * 8 * RS + c1];
                mma16816(acc[0][g], A00, A01, A02, A03, b0, b1);
                mma16816(acc[1][g], A10, A11, A12, A13, b0, b1);
            }
        }

        const int zlo = z0 + rowin;
        const int zhi = zlo + 8;
        #pragma unroll
        for (int xi = 0; xi < 2; xi++) {
            if (xi == 1 && !hasx1) break;
            const int x = xi ? x1 : x0;
            float* const obase = outT + x * NB;
            #pragma unroll
            for (int g = 0; g < 6; g++) {
                const int y = 8 * g + 2 * qc;
                if (y < NB) {
                    obase[(size_t)y * NXZ + zlo] = acc[xi][g][0] * scale;
                    if (zhi < NB) obase[(size_t)y * NXZ + zhi] = acc[xi][g][2] * scale;
                }
                if (y + 1 < NB) {
                    obase[(size_t)(y + 1) * NXZ + zlo] = acc[xi][g][1] * scale;
                    if (zhi < NB) obase[(size_t)(y + 1) * NXZ + zhi] = acc[xi][g][3] * scale;
                }
            }
        }
    }
}

// ---------------------------------------------------------------------------
// Launch
// ---------------------------------------------------------------------------
extern "C" void kernel_launch(void* const* d_in, const int* in_sizes, int n_in,
                              void* d_out, int out_size)
{
    const float *emb = nullptr, *W = nullptr, *bias = nullptr, *ls = nullptr;
    for (int i = 0; i < n_in; i++) {
        switch (in_sizes[i]) {
            case TOKENS * HID:   emb  = (const float*)d_in[i]; break;
            case OUTC * HID:     W    = (const float*)d_in[i]; break;
            case OUTC:           bias = (const float*)d_in[i]; break;
            case 1:              ls   = (const float*)d_in[i]; break;
            default: break;
        }
    }

    cudaFuncSetAttribute(gemm_softplus_tf32,
                         cudaFuncAttributeMaxDynamicSharedMemorySize,
                         SM1_BYTES);
    dim3 g1(OUTC / 128, TOKENS / 128);  // 246 x 16
    gemm_softplus_tf32<<<g1, 256, SM1_BYTES>>>(W, emb, bias);

    cudaFuncSetAttribute(triple_mma_kernel,
                         cudaFuncAttributeMaxDynamicSharedMemorySize,
                         SM2_BYTES);
    triple_mma_kernel<<<TOKENS, 256, SM2_BYTES>>>(ls, (float*)d_out);
}

// round 9
// speedup vs baseline: 1.1032x; 1.1032x over previous
#include <cuda_runtime.h>
#include <cuda_bf16.h>
#include <math.h>
#include <stdint.h>

// Problem constants
#define TOKENS 2048
#define HID 256
#define NB 41
#define CBIN 123
#define OUTC (CBIN * HID)    // 31488
#define OPT (NB * NB * NB)   // 68921
#define NXZ (NB * NB)        // 1681

// Scratch: bin = softplus(emb @ W^T + b), token-major bf16
__device__ __nv_bfloat16 g_bin[(size_t)TOKENS * OUTC];

// ---------------------------------------------------------------------------
// Shared helpers
// ---------------------------------------------------------------------------
__device__ __forceinline__ uint32_t pack_bf16(float a, float b) {
    __nv_bfloat162 t = __float22bfloat162_rn(make_float2(a, b));
    return *(uint32_t*)&t;
}
__device__ __forceinline__ void mma16816(float* d,
                                         uint32_t a0, uint32_t a1,
                                         uint32_t a2, uint32_t a3,
                                         uint32_t b0, uint32_t b1) {
    asm volatile(
        "mma.sync.aligned.m16n8k16.row.col.f32.bf16.bf16.f32 "
        "{%0,%1,%2,%3}, {%4,%5,%6,%7}, {%8,%9}, {%0,%1,%2,%3};"
        : "+f"(d[0]), "+f"(d[1]), "+f"(d[2]), "+f"(d[3])
        : "r"(a0), "r"(a1), "r"(a2), "r"(a3), "r"(b0), "r"(b1));
}
__device__ __forceinline__ float softplusf(float x) {
    return fmaxf(x, 0.0f) + log1pf(expf(-fabsf(x)));
}

// ---------------------------------------------------------------------------
// Stage 1: bf16 tensor-core GEMM + softplus + bf16 store
//   C[t, o] = softplus( sum_k emb[t,k] * W[o,k] + b[o] )
//   emb/W rounded to bf16 (rn) at STS. CTA tile 128(t) x 128(o), BK=16,
//   double-buffered LDG->cvt->STS, 8 warps of 64x32 via m16n8k16.
// ---------------------------------------------------------------------------
#define RS1 12    // SMEM row stride in u32; (12*r+c) mod 32 all-distinct

__global__ void __launch_bounds__(256, 2) gemm_softplus_bf16(
    const float* __restrict__ W, const float* __restrict__ emb,
    const float* __restrict__ bias)
{
    __shared__ uint32_t As[2][128 * RS1];  // emb tiles (bf16x2), k-contig
    __shared__ uint32_t Bs[2][128 * RS1];  // W tiles

    const int t0 = blockIdx.y * 128;
    const int o0 = blockIdx.x * 128;
    const int tid = threadIdx.x;
    const int wid = tid >> 5, lane = tid & 31;
    const int wm = (wid & 1) * 64;       // t offset of warp tile
    const int wn = (wid >> 1) * 32;      // o offset of warp tile
    const int r = lane >> 2, qc = lane & 3;

    // Loader: row = tid>>1, f32 col blocks q0 and q0+8 (q0 in {0,4})
    const int lrow = tid >> 1;
    const int q0 = (tid & 1) * 4;
    const int q1 = q0 + 8;
    const int uc0 = q0 >> 1;             // u32 col of first pair block
    const int uc1 = q1 >> 1;
    const float* embRow = emb + (size_t)(t0 + lrow) * HID;
    const float* wRow = W + (size_t)(o0 + lrow) * HID;

    float acc[4][4][4];
    #pragma unroll
    for (int mt = 0; mt < 4; mt++)
        #pragma unroll
        for (int nt = 0; nt < 4; nt++)
            #pragma unroll
            for (int q = 0; q < 4; q++) acc[mt][nt][q] = 0.0f;

    // Prologue: load+convert k-chunk 0 into buffer 0
    {
        float4 ea = *(const float4*)(embRow + q0);
        float4 eb = *(const float4*)(embRow + q1);
        float4 wa = *(const float4*)(wRow + q0);
        float4 wb = *(const float4*)(wRow + q1);
        uint32_t* ap = &As[0][lrow * RS1];
        uint32_t* bp = &Bs[0][lrow * RS1];
        ap[uc0] = pack_bf16(ea.x, ea.y); ap[uc0 + 1] = pack_bf16(ea.z, ea.w);
        ap[uc1] = pack_bf16(eb.x, eb.y); ap[uc1 + 1] = pack_bf16(eb.z, eb.w);
        bp[uc0] = pack_bf16(wa.x, wa.y); bp[uc0 + 1] = pack_bf16(wa.z, wa.w);
        bp[uc1] = pack_bf16(wb.x, wb.y); bp[uc1 + 1] = pack_bf16(wb.z, wb.w);
    }
    __syncthreads();

    float4 ea, eb, wa, wb;
    #pragma unroll 1
    for (int it = 0; it < 16; it++) {
        const int cur = it & 1;
        if (it < 15) {
            const int k0 = (it + 1) * 16;
            ea = *(const float4*)(embRow + k0 + q0);
            eb = *(const float4*)(embRow + k0 + q1);
            wa = *(const float4*)(wRow + k0 + q0);
            wb = *(const float4*)(wRow + k0 + q1);
        }

        const uint32_t* Ac = As[cur];
        const uint32_t* Bc = Bs[cur];
        uint32_t a[4][4], b[4][2];
        #pragma unroll
        for (int mt = 0; mt < 4; mt++) {
            const uint32_t* p = &Ac[(wm + mt * 16 + r) * RS1];
            a[mt][0] = p[qc];
            a[mt][1] = p[8 * RS1 + qc];
            a[mt][2] = p[qc + 4];
            a[mt][3] = p[8 * RS1 + qc + 4];
        }
        #pragma unroll
        for (int nt = 0; nt < 4; nt++) {
            const uint32_t* p = &Bc[(wn + nt * 8 + r) * RS1];
            b[nt][0] = p[qc];
            b[nt][1] = p[qc + 4];
        }
        #pragma unroll
        for (int mt = 0; mt < 4; mt++)
            #pragma unroll
            for (int nt = 0; nt < 4; nt++)
                mma16816(acc[mt][nt], a[mt][0], a[mt][1], a[mt][2], a[mt][3],
                         b[nt][0], b[nt][1]);

        if (it < 15) {
            const int nxt = cur ^ 1;
            uint32_t* ap = &As[nxt][lrow * RS1];
            uint32_t* bp = &Bs[nxt][lrow * RS1];
            ap[uc0] = pack_bf16(ea.x, ea.y); ap[uc0 + 1] = pack_bf16(ea.z, ea.w);
            ap[uc1] = pack_bf16(eb.x, eb.y); ap[uc1 + 1] = pack_bf16(eb.z, eb.w);
            bp[uc0] = pack_bf16(wa.x, wa.y); bp[uc0 + 1] = pack_bf16(wa.z, wa.w);
            bp[uc1] = pack_bf16(wb.x, wb.y); bp[uc1 + 1] = pack_bf16(wb.z, wb.w);
            __syncthreads();
        }
    }

    // Epilogue: +bias, softplus, pack bf16x2, store token-major
    uint32_t* gb = (uint32_t*)g_bin;
    #pragma unroll
    for (int mt = 0; mt < 4; mt++) {
        const int tA = t0 + wm + mt * 16 + r;
        const size_t row0 = (size_t)tA * (OUTC / 2);
        const size_t row1 = (size_t)(tA + 8) * (OUTC / 2);
        #pragma unroll
        for (int nt = 0; nt < 4; nt++) {
            const int o = o0 + wn + nt * 8 + 2 * qc;
            const float2 bi = *(const float2*)(bias + o);
            float s0 = softplusf(acc[mt][nt][0] + bi.x);
            float s1 = softplusf(acc[mt][nt][1] + bi.y);
            float s2 = softplusf(acc[mt][nt][2] + bi.x);
            float s3 = softplusf(acc[mt][nt][3] + bi.y);
            gb[row0 + (o >> 1)] = pack_bf16(s0, s1);
            gb[row1 + (o >> 1)] = pack_bf16(s2, s3);
        }
    }
}

// ---------------------------------------------------------------------------
// Stage 2: per-token triple contraction via warp mma.sync (bf16, f32 acc)
//   Job = (z-tile of 16, x-pair). UNCHANGED from round 8 (437 us measured).
// ---------------------------------------------------------------------------
#define RS 132           // SMEM row stride in u32 (132 % 32 == 4)
#define EYB 41
#define EZB 89
#define SM2_U32 (137 * RS)
#define SM2_BYTES (SM2_U32 * 4)   // 72336

__device__ __forceinline__ uint32_t bmul2(uint32_t a, uint32_t b) {
    uint32_t d;
    asm("mul.bf16x2 %0, %1, %2;" : "=r"(d) : "r"(a), "r"(b));
    return d;
}

__global__ void __launch_bounds__(256, 2) triple_mma_kernel(
    const float* __restrict__ ls, float* __restrict__ out)
{
    extern __shared__ uint32_t sm[];
    const int tid = threadIdx.x;
    const int wid = tid >> 5;
    const int lid = tid & 31;
    const int rowin = lid >> 2;
    const int qc = lid & 3;
    const int t = blockIdx.x;

    const uint4* src = (const uint4*)(g_bin + (size_t)t * OUTC);
    for (int i = tid; i < CBIN * 32; i += 256) {
        const int cc = i >> 5;
        const int j = i & 31;
        const int dr = cc + (cc >= 82 ? 7 : 0);
        *(uint4*)&sm[dr * RS + j * 4] = src[i];
    }
    for (int i = tid; i < 7 * RS; i += 256) {
        sm[82 * RS + i] = 0u;
        sm[130 * RS + i] = 0u;
    }
    __syncthreads();

    const float scale = expf(ls[0]);
    float* __restrict__ outT = out + (size_t)t * OPT;

    for (int j = wid; j < 63; j += 8) {
        const int zt = j / 21;
        const int xp = j - zt * 21;
        const int x0 = 2 * xp;
        const bool hasx1 = (x0 + 1 < NB);
        const int x1 = hasx1 ? (x0 + 1) : (NB - 1);
        const int z0 = zt * 16;

        float acc[2][6][4];
        #pragma unroll
        for (int xi = 0; xi < 2; xi++)
            #pragma unroll
            for (int g = 0; g < 6; g++)
                #pragma unroll
                for (int qq = 0; qq < 4; qq++) acc[xi][g][qq] = 0.0f;

        const uint32_t* __restrict__ ex0p = sm + x0 * RS;
        const uint32_t* __restrict__ ex1p = sm + x1 * RS;
        const uint32_t* __restrict__ ezA = sm + (EZB + z0 + rowin) * RS;
        const uint32_t* __restrict__ ezB = ezA + 8 * RS;
        const uint32_t* __restrict__ eyp = sm + (EYB + rowin) * RS;

        #pragma unroll
        for (int k = 0; k < 16; k++) {
            const int c0 = k * 8 + qc;
            const int c1 = c0 + 4;
            const uint32_t ez0 = ezA[c0], ez1 = ezB[c0];
            const uint32_t ez2 = ezA[c1], ez3 = ezB[c1];
            const uint32_t exa0 = ex0p[c0], exa1 = ex0p[c1];
            const uint32_t exb0 = ex1p[c0], exb1 = ex1p[c1];
            const uint32_t A00 = bmul2(ez0, exa0), A01 = bmul2(ez1, exa0);
            const uint32_t A02 = bmul2(ez2, exa1), A03 = bmul2(ez3, exa1);
            const uint32_t A10 = bmul2(ez0, exb0), A11 = bmul2(ez1, exb0);
            const uint32_t A12 = bmul2(ez2, exb1), A13 = bmul2(ez3, exb1);
            #pragma unroll
            for (int g = 0; g < 6; g++) {
                const uint32_t b0 = eyp[g * 8 * RS + c0];
                const uint32_t b1 = eyp[g * 8 * RS + c1];
                mma16816(acc[0][g], A00, A01, A02, A03, b0, b1);
                mma16816(acc[1][g], A10, A11, A12, A13, b0, b1);
            }
        }

        const int zlo = z0 + rowin;
        const int zhi = zlo + 8;
        #pragma unroll
        for (int xi = 0; xi < 2; xi++) {
            if (xi == 1 && !hasx1) break;
            const int x = xi ? x1 : x0;
            float* const obase = outT + x * NB;
            #pragma unroll
            for (int g = 0; g < 6; g++) {
                const int y = 8 * g + 2 * qc;
                if (y < NB) {
                    obase[(size_t)y * NXZ + zlo] = acc[xi][g][0] * scale;
                    if (zhi < NB) obase[(size_t)y * NXZ + zhi] = acc[xi][g][2] * scale;
                }
                if (y + 1 < NB) {
                    obase[(size_t)(y + 1) * NXZ + zlo] = acc[xi][g][1] * scale;
                    if (zhi < NB) obase[(size_t)(y + 1) * NXZ + zhi] = acc[xi][g][3] * scale;
                }
            }
        }
    }
}

// ---------------------------------------------------------------------------
// Launch
// ---------------------------------------------------------------------------
extern "C" void kernel_launch(void* const* d_in, const int* in_sizes, int n_in,
                              void* d_out, int out_size)
{
    const float *emb = nullptr, *W = nullptr, *bias = nullptr, *ls = nullptr;
    for (int i = 0; i < n_in; i++) {
        switch (in_sizes[i]) {
            case TOKENS * HID:   emb  = (const float*)d_in[i]; break;
            case OUTC * HID:     W    = (const float*)d_in[i]; break;
            case OUTC:           bias = (const float*)d_in[i]; break;
            case 1:              ls   = (const float*)d_in[i]; break;
            default: break;
        }
    }

    dim3 g1(OUTC / 128, TOKENS / 128);  // 246 x 16
    gemm_softplus_bf16<<<g1, 256>>>(W, emb, bias);

    cudaFuncSetAttribute(triple_mma_kernel,
                         cudaFuncAttributeMaxDynamicSharedMemorySize,
                         SM2_BYTES);
    triple_mma_kernel<<<TOKENS, 256, SM2_BYTES>>>(ls, (float*)d_out);
}